// round 1
// baseline (speedup 1.0000x reference)
#include <cuda_runtime.h>
#include <math.h>
#include <stdint.h>

// Problem constants
#define NX 25
#define NY 7
#define NZ 6
#define NW 5
#define F_ELEMS (5 * NX * NY * NZ * NW)      // 26250  (one grid[j] slice)
#define THETA_ELEMS (256 * 256)              // 65536
#define GRID_ITEMS 2000                      // LEN_DATASET / 5
#define GRID_ELEMS ((size_t)GRID_ITEMS * F_ELEMS)  // 52,500,000

// Accumulators: [0..4] = s[n] = <x[n], A>, [5] = sum|A|
__device__ float g_acc[6];

__global__ void zero_acc_kernel() {
    if (threadIdx.x < 6) g_acc[threadIdx.x] = 0.0f;
}

// Grid-stride: computes the 5 projections + sum|theta|, and copies theta to out.
__global__ void reduce_kernel(const float* __restrict__ x,
                              const float* __restrict__ theta,
                              float* __restrict__ out_theta) {
    float acc[6] = {0.f, 0.f, 0.f, 0.f, 0.f, 0.f};
    const int stride = gridDim.x * blockDim.x;
    for (int k = blockIdx.x * blockDim.x + threadIdx.x; k < THETA_ELEMS; k += stride) {
        float a = theta[k];
        out_theta[k] = a;                     // free theta passthrough
        acc[5] += fabsf(a);
#pragma unroll
        for (int n = 0; n < 5; n++)
            acc[n] += x[n * THETA_ELEMS + k] * a;
    }

    __shared__ float sm[6][32];
    const int lane = threadIdx.x & 31;
    const int warp = threadIdx.x >> 5;
#pragma unroll
    for (int i = 0; i < 6; i++) {
        float v = acc[i];
#pragma unroll
        for (int o = 16; o; o >>= 1) v += __shfl_down_sync(0xffffffffu, v, o);
        if (lane == 0) sm[i][warp] = v;
    }
    __syncthreads();
    const int nwarps = blockDim.x >> 5;
    if (warp == 0) {
#pragma unroll
        for (int i = 0; i < 6; i++) {
            float v = (lane < nwarps) ? sm[i][lane] : 0.f;
#pragma unroll
            for (int o = 16; o; o >>= 1) v += __shfl_down_sync(0xffffffffu, v, o);
            if (lane == 0) atomicAdd(&g_acc[i], v);
        }
    }
}

// Single block: compute f_grid (26250 elems), write slice j, fused loss reduce.
__global__ void fgrid_loss_kernel(const int* __restrict__ jp,
                                  float* __restrict__ out) {
    const float TWO_PI = 6.2831853071795864769f;
    const float dx = TWO_PI / 24.0f;   // x step
    const float dy = 0.18f / 6.0f;     // 0.03
    const float dz = 0.18f / 5.0f;     // 0.036
    const float dw = 0.2f  / 4.0f;     // 0.05
    const float wbase = dx * dy * dz * dw;

    const int j = jp[0];
    float s_local[5];
#pragma unroll
    for (int n = 0; n < 5; n++) s_local[n] = g_acc[n];

    float* gout = out + 1 + THETA_ELEMS + (size_t)j * F_ELEMS;

    float partial = 0.0f;
    for (int i = threadIdx.x; i < F_ELEMS; i += blockDim.x) {
        int d = i % NW;
        int c = (i / NW) % NZ;
        int b = (i / (NW * NZ)) % NY;
        int a = (i / (NW * NZ * NY)) % NX;
        int n = i / (NW * NZ * NY * NX);

        float xv = TWO_PI * (float)a / 24.0f;
        float yv = -0.09f + dy * (float)b;
        float zv = -0.09f + dz * (float)c;
        float wv = 0.9f + dw * (float)d;

        float arg = s_local[n] * cosf(xv) * wv + yv + zv;
        float f = expf(-arg * arg);
        gout[i] = f;

        float w = wbase;
        if (a == 0 || a == NX - 1) w *= 0.5f;
        if (b == 0 || b == NY - 1) w *= 0.5f;
        if (c == 0 || c == NZ - 1) w *= 0.5f;
        if (d == 0 || d == NW - 1) w *= 0.5f;
        partial += f * w;
    }

    // block reduction
    __shared__ float sm[32];
    const int lane = threadIdx.x & 31;
    const int warp = threadIdx.x >> 5;
    float v = partial;
#pragma unroll
    for (int o = 16; o; o >>= 1) v += __shfl_down_sync(0xffffffffu, v, o);
    if (lane == 0) sm[warp] = v;
    __syncthreads();
    const int nwarps = blockDim.x >> 5;
    if (warp == 0) {
        float t = (lane < nwarps) ? sm[lane] : 0.f;
#pragma unroll
        for (int o = 16; o; o >>= 1) t += __shfl_down_sync(0xffffffffu, t, o);
        if (lane == 0) out[0] = t - 0.5f * g_acc[5];
    }
}

extern "C" void kernel_launch(void* const* d_in, const int* in_sizes, int n_in,
                              void* d_out, int out_size) {
    const float* x     = (const float*)d_in[0];   // [5,256,256]
    const float* theta = (const float*)d_in[1];   // [1,256,256]
    const float* grid  = (const float*)d_in[2];   // [2000,5,25,7,6,5]
    const int*   jp    = (const int*)d_in[3];     // scalar j

    float* out = (float*)d_out;
    // out layout: [0]=loss, [1 .. 65536]=theta[0], [65537 ..]=grid_new

    zero_acc_kernel<<<1, 32>>>();
    reduce_kernel<<<128, 256>>>(x, theta, out + 1);

    // bulk grid copy (dominant cost ~420 MB traffic)
    cudaMemcpyAsync(out + 1 + THETA_ELEMS, grid, GRID_ELEMS * sizeof(float),
                    cudaMemcpyDeviceToDevice, 0);

    // overwrite slice j + loss epilogue (after copy so slice write wins)
    fgrid_loss_kernel<<<1, 1024>>>(jp, out);
}

// round 3
// speedup vs baseline: 1.7051x; 1.7051x over previous
#include <cuda_runtime.h>
#include <math.h>
#include <stdint.h>

// Problem constants
#define NX 25
#define NY 7
#define NZ 6
#define NW 5
#define F_ELEMS (5 * NX * NY * NZ * NW)            // 26250 (one grid[j] slice)
#define THETA_ELEMS (256 * 256)                    // 65536
#define GRID_ITEMS 2000                            // LEN_DATASET / 5
#define GRID_ELEMS ((size_t)GRID_ITEMS * F_ELEMS)  // 52,500,000 floats

// Output layout (floats): [0]=loss, [1..65536]=theta, [65537..]=grid_new
#define OUT_GRID_OFF (1 + THETA_ELEMS)             // 65537

// Reduction geometry
#define RED_BLOCKS 64
#define RED_THREADS 256

// Copy geometry: peel 3 floats so destination is 16B-aligned.
// Aligned region: src = grid+3, dst = out+65540, count = GRID_ELEMS-3
#define PEEL 3
#define ALIGNED_FLOATS (GRID_ELEMS - PEEL)         // 52,499,997
#define NVEC4 (ALIGNED_FLOATS / 4)                 // 13,124,999 float4 stores

#define COPY_BLOCKS 2368                           // 148 SMs * 16
#define COPY_THREADS 256

// Per-block partials: [block][0..4]=s[n], [5]=sum|theta|. Overwritten every
// replay (no zeroing needed, no atomics).
__device__ float g_part[RED_BLOCKS][6];

// ---------------------------------------------------------------------------
// Fused kernel: blocks [0, RED_BLOCKS) do the 5 projections + sum|theta| +
// theta passthrough; blocks [RED_BLOCKS, ...) stream-copy the 210MB grid.
// ---------------------------------------------------------------------------
__global__ void __launch_bounds__(256) fused_main_kernel(
    const float* __restrict__ x,
    const float* __restrict__ theta,
    const float* __restrict__ grid,
    float* __restrict__ out) {

    if (blockIdx.x < RED_BLOCKS) {
        // ---- reduction + theta passthrough ----
        float acc[6] = {0.f, 0.f, 0.f, 0.f, 0.f, 0.f};
        const int stride = RED_BLOCKS * RED_THREADS;
        for (int k = blockIdx.x * RED_THREADS + threadIdx.x; k < THETA_ELEMS; k += stride) {
            float a = __ldg(theta + k);
            out[1 + k] = a;
            acc[5] += fabsf(a);
#pragma unroll
            for (int n = 0; n < 5; n++)
                acc[n] += __ldg(x + n * THETA_ELEMS + k) * a;
        }

        __shared__ float sm[6][8];
        const int lane = threadIdx.x & 31;
        const int warp = threadIdx.x >> 5;   // 0..7
#pragma unroll
        for (int i = 0; i < 6; i++) {
            float v = acc[i];
#pragma unroll
            for (int o = 16; o; o >>= 1) v += __shfl_down_sync(0xffffffffu, v, o);
            if (lane == 0) sm[i][warp] = v;
        }
        __syncthreads();
        if (warp == 0 && lane < 6) {
            float v = 0.f;
#pragma unroll
            for (int w = 0; w < 8; w++) v += sm[lane][w];
            g_part[blockIdx.x][lane] = v;
        }
        return;
    }

    // ---- grid copy: dst 16B-aligned float4 stores, scalar loads ----
    const int cb = blockIdx.x - RED_BLOCKS;
    const long tid = (long)cb * COPY_THREADS + threadIdx.x;
    const long nthreads = (long)COPY_BLOCKS * COPY_THREADS;

    const float* __restrict__ src = grid + PEEL;
    float4* __restrict__ dst4 = (float4*)(out + OUT_GRID_OFF + PEEL);

    for (long i = tid; i < (long)NVEC4; i += nthreads) {
        long b = i * 4;
        float4 v;
        v.x = __ldg(src + b + 0);
        v.y = __ldg(src + b + 1);
        v.z = __ldg(src + b + 2);
        v.w = __ldg(src + b + 3);
        dst4[i] = v;
    }

    // peel head (3 floats) + tail (1 float): one thread
    if (cb == 0 && threadIdx.x == 0) {
#pragma unroll
        for (int p = 0; p < PEEL; p++)
            out[OUT_GRID_OFF + p] = grid[p];
        out[OUT_GRID_OFF + PEEL + (long)NVEC4 * 4] =
            grid[PEEL + (long)NVEC4 * 4];
    }
}

// ---------------------------------------------------------------------------
// Epilogue: reduce partials, compute f_grid slice j + loss.
// ---------------------------------------------------------------------------
__global__ void __launch_bounds__(1024) fgrid_loss_kernel(
    const int* __restrict__ jp, float* __restrict__ out) {

    const float TWO_PI = 6.2831853071795864769f;
    const float dxs = TWO_PI / 24.0f;
    const float dy = 0.18f / 6.0f;     // 0.03
    const float dz = 0.18f / 5.0f;     // 0.036
    const float dw = 0.2f / 4.0f;      // 0.05
    const float wbase = dxs * dy * dz * dw;

    // sum the 64 per-block partials (registers; reads hit L2)
    float s_local[5];
    float sum_abs = 0.f;
#pragma unroll
    for (int n = 0; n < 5; n++) s_local[n] = 0.f;
    for (int b = 0; b < RED_BLOCKS; b++) {
#pragma unroll
        for (int n = 0; n < 5; n++) s_local[n] += g_part[b][n];
        sum_abs += g_part[b][5];
    }

    const int j = jp[0];
    float* gout = out + OUT_GRID_OFF + (size_t)j * F_ELEMS;

    float partial = 0.0f;
    for (int i = threadIdx.x; i < F_ELEMS; i += blockDim.x) {
        int d = i % NW;
        int c = (i / NW) % NZ;
        int b = (i / (NW * NZ)) % NY;
        int a = (i / (NW * NZ * NY)) % NX;
        int n = i / (NW * NZ * NY * NX);

        float xv = TWO_PI * (float)a / 24.0f;
        float yv = -0.09f + dy * (float)b;
        float zv = -0.09f + dz * (float)c;
        float wv = 0.9f + dw * (float)d;

        float arg = s_local[n] * cosf(xv) * wv + yv + zv;
        float f = expf(-arg * arg);
        gout[i] = f;

        float w = wbase;
        if (a == 0 || a == NX - 1) w *= 0.5f;
        if (b == 0 || b == NY - 1) w *= 0.5f;
        if (c == 0 || c == NZ - 1) w *= 0.5f;
        if (d == 0 || d == NW - 1) w *= 0.5f;
        partial += f * w;
    }

    __shared__ float sm[32];
    const int lane = threadIdx.x & 31;
    const int warp = threadIdx.x >> 5;
    float v = partial;
#pragma unroll
    for (int o = 16; o; o >>= 1) v += __shfl_down_sync(0xffffffffu, v, o);
    if (lane == 0) sm[warp] = v;
    __syncthreads();
    if (warp == 0) {
        float t = (lane < (blockDim.x >> 5)) ? sm[lane] : 0.f;
#pragma unroll
        for (int o = 16; o; o >>= 1) t += __shfl_down_sync(0xffffffffu, t, o);
        if (lane == 0) out[0] = t - 0.5f * sum_abs;
    }
}

extern "C" void kernel_launch(void* const* d_in, const int* in_sizes, int n_in,
                              void* d_out, int out_size) {
    const float* x     = (const float*)d_in[0];   // [5,256,256]
    const float* theta = (const float*)d_in[1];   // [1,256,256]
    const float* grid  = (const float*)d_in[2];   // [2000,5,25,7,6,5]
    const int*   jp    = (const int*)d_in[3];     // scalar j

    float* out = (float*)d_out;

    fused_main_kernel<<<RED_BLOCKS + COPY_BLOCKS, 256>>>(x, theta, grid, out);
    fgrid_loss_kernel<<<1, 1024>>>(jp, out);
}

// round 4
// speedup vs baseline: 2.1815x; 1.2794x over previous
#include <cuda_runtime.h>
#include <math.h>
#include <stdint.h>

// Problem constants
#define NX 25
#define NY 7
#define NZ 6
#define NW 5
#define F_ELEMS (5 * NX * NY * NZ * NW)            // 26250 (one grid[j] slice)
#define THETA_ELEMS (256 * 256)                    // 65536
#define GRID_ITEMS 2000                            // LEN_DATASET / 5
#define GRID_ELEMS ((size_t)GRID_ITEMS * F_ELEMS)  // 52,500,000 floats

// Output layout (floats): [0]=loss, [1..65536]=theta, [65537..]=grid_new
#define OUT_GRID_OFF (1 + THETA_ELEMS)             // 65537

// Reduction geometry
#define RED_BLOCKS 128
#define RED_THREADS 256

// Copy geometry: peel 3 floats so destination is 16B-aligned.
#define PEEL 3
#define ALIGNED_FLOATS (GRID_ELEMS - PEEL)         // 52,499,997
#define NVEC4 (ALIGNED_FLOATS / 4)                 // 13,124,999 float4 stores

#define COPY_BLOCKS 2368                           // 148 SMs * 16
#define COPY_THREADS 256

// Per-block partials: [block][0..4]=s[n], [5]=sum|theta|. Overwritten every
// replay (no zeroing needed, no atomics).
__device__ float g_part[RED_BLOCKS][6];

// ---------------------------------------------------------------------------
// k1: 5 projections + sum|theta| partials, theta passthrough.
// ---------------------------------------------------------------------------
__global__ void __launch_bounds__(RED_THREADS) reduce_kernel(
    const float* __restrict__ x,
    const float* __restrict__ theta,
    float* __restrict__ out) {

    float acc[6] = {0.f, 0.f, 0.f, 0.f, 0.f, 0.f};
    const int stride = RED_BLOCKS * RED_THREADS;
    for (int k = blockIdx.x * RED_THREADS + threadIdx.x; k < THETA_ELEMS; k += stride) {
        float a = __ldg(theta + k);
        out[1 + k] = a;
        acc[5] += fabsf(a);
#pragma unroll
        for (int n = 0; n < 5; n++)
            acc[n] += __ldg(x + n * THETA_ELEMS + k) * a;
    }

    __shared__ float sm[6][8];
    const int lane = threadIdx.x & 31;
    const int warp = threadIdx.x >> 5;   // 0..7
#pragma unroll
    for (int i = 0; i < 6; i++) {
        float v = acc[i];
#pragma unroll
        for (int o = 16; o; o >>= 1) v += __shfl_down_sync(0xffffffffu, v, o);
        if (lane == 0) sm[i][warp] = v;
    }
    __syncthreads();
    if (warp == 0 && lane < 6) {
        float v = 0.f;
#pragma unroll
        for (int w = 0; w < 8; w++) v += sm[lane][w];
        g_part[blockIdx.x][lane] = v;
    }
}

// ---------------------------------------------------------------------------
// k2: block 0 = fgrid slice j + loss (fast-math intrinsics, runs under the
// copy's shadow). blocks >= 1 = grid copy that SKIPS slice j floats.
// ---------------------------------------------------------------------------
__global__ void __launch_bounds__(1024) fused_copy_fgrid_kernel(
    const float* __restrict__ grid,
    const int* __restrict__ jp,
    float* __restrict__ out) {

    const int j = __ldg(jp);
    const long lo = (long)j * F_ELEMS;        // slice-j float range in grid
    const long hi = lo + F_ELEMS;

    if (blockIdx.x == 0) {
        // ---- final reduce of partials: 6 warps, one value each ----
        __shared__ float s_final[6];
        const int lane = threadIdx.x & 31;
        const int warp = threadIdx.x >> 5;
        if (warp < 6) {
            float v = 0.f;
            for (int b = lane; b < RED_BLOCKS; b += 32) v += g_part[b][warp];
#pragma unroll
            for (int o = 16; o; o >>= 1) v += __shfl_down_sync(0xffffffffu, v, o);
            if (lane == 0) s_final[warp] = v;
        }
        __syncthreads();

        float s_local[5];
#pragma unroll
        for (int n = 0; n < 5; n++) s_local[n] = s_final[n];
        const float sum_abs = s_final[5];

        const float TWO_PI = 6.2831853071795864769f;
        const float dxs = TWO_PI / 24.0f;
        const float dy = 0.18f / 6.0f;     // 0.03
        const float dz = 0.18f / 5.0f;     // 0.036
        const float dw = 0.2f / 4.0f;      // 0.05
        const float wbase = dxs * dy * dz * dw;

        float* gout = out + OUT_GRID_OFF + lo;

        float partial = 0.0f;
        for (int i = threadIdx.x; i < F_ELEMS; i += blockDim.x) {
            int d = i % NW;
            int c = (i / NW) % NZ;
            int b = (i / (NW * NZ)) % NY;
            int a = (i / (NW * NZ * NY)) % NX;
            int n = i / (NW * NZ * NY * NX);

            float xv = TWO_PI * (float)a / 24.0f;
            float yv = -0.09f + dy * (float)b;
            float zv = -0.09f + dz * (float)c;
            float wv = 0.9f + dw * (float)d;

            float arg = s_local[n] * __cosf(xv) * wv + yv + zv;
            float f = __expf(-arg * arg);
            gout[i] = f;

            float w = wbase;
            if (a == 0 || a == NX - 1) w *= 0.5f;
            if (b == 0 || b == NY - 1) w *= 0.5f;
            if (c == 0 || c == NZ - 1) w *= 0.5f;
            if (d == 0 || d == NW - 1) w *= 0.5f;
            partial += f * w;
        }

        __shared__ float sm[32];
        float v = partial;
#pragma unroll
        for (int o = 16; o; o >>= 1) v += __shfl_down_sync(0xffffffffu, v, o);
        if (lane == 0) sm[warp] = v;
        __syncthreads();
        if (warp == 0) {
            float t = (lane < (int)(blockDim.x >> 5)) ? sm[lane] : 0.f;
#pragma unroll
            for (int o = 16; o; o >>= 1) t += __shfl_down_sync(0xffffffffu, t, o);
            if (lane == 0) out[0] = t - 0.5f * sum_abs;
        }
        return;
    }

    // ---- grid copy (skip slice j): dst-aligned float4 stores ----
    const int cb = blockIdx.x - 1;
    const long tid = (long)cb * 1024 + threadIdx.x;
    const long nthreads = (long)COPY_BLOCKS * 1024;

    const float* __restrict__ src = grid + PEEL;
    float4* __restrict__ dst4 = (float4*)(out + OUT_GRID_OFF + PEEL);

    for (long i = tid; i < (long)NVEC4; i += nthreads) {
        long b = i * 4 + PEEL;                // absolute float index in grid
        if (b + 4 <= lo || b >= hi) {
            // fully outside slice j: plain vector copy (common path)
            float4 v;
            v.x = __ldg(src + i * 4 + 0);
            v.y = __ldg(src + i * 4 + 1);
            v.z = __ldg(src + i * 4 + 2);
            v.w = __ldg(src + i * 4 + 3);
            dst4[i] = v;
        } else if (b >= lo && b + 4 <= hi) {
            // fully inside slice j: fgrid block writes it
        } else {
            // straddles a slice boundary: scalar copy of outside floats
#pragma unroll
            for (int p = 0; p < 4; p++) {
                long e = b + p;
                if (e < lo || e >= hi)
                    out[OUT_GRID_OFF + e] = __ldg(grid + e);
            }
        }
    }

    // peel head (3 floats) + tail (1 float): one thread, slice-aware
    if (cb == 0 && threadIdx.x == 0) {
#pragma unroll
        for (int p = 0; p < PEEL; p++)
            if (p < lo || p >= hi)
                out[OUT_GRID_OFF + p] = grid[p];
        long tail = PEEL + (long)NVEC4 * 4;
        if (tail < lo || tail >= hi)
            out[OUT_GRID_OFF + tail] = grid[tail];
    }
}

extern "C" void kernel_launch(void* const* d_in, const int* in_sizes, int n_in,
                              void* d_out, int out_size) {
    const float* x     = (const float*)d_in[0];   // [5,256,256]
    const float* theta = (const float*)d_in[1];   // [1,256,256]
    const float* grid  = (const float*)d_in[2];   // [2000,5,25,7,6,5]
    const int*   jp    = (const int*)d_in[3];     // scalar j

    float* out = (float*)d_out;

    reduce_kernel<<<RED_BLOCKS, RED_THREADS>>>(x, theta, out);
    fused_copy_fgrid_kernel<<<1 + COPY_BLOCKS, 1024>>>(grid, jp, out);
}

// round 5
// speedup vs baseline: 2.3400x; 1.0726x over previous
#include <cuda_runtime.h>
#include <math.h>
#include <stdint.h>

// Problem constants
#define NX 25
#define NY 7
#define NZ 6
#define NW 5
#define F_ELEMS (5 * NX * NY * NZ * NW)            // 26250 (one grid[j] slice)
#define THETA_ELEMS (256 * 256)                    // 65536
#define GRID_ITEMS 2000                            // LEN_DATASET / 5
#define GRID_ELEMS (GRID_ITEMS * F_ELEMS)          // 52,500,000 floats (fits int)

// Output layout (floats): [0]=loss, [1..65536]=theta, [65537..]=grid_new
#define OUT_GRID_OFF (1 + THETA_ELEMS)             // 65537

// Copy geometry: peel 3 floats so destination is 16B-aligned.
#define PEEL 3
#define NVEC4 ((GRID_ELEMS - PEEL) / 4)            // 13,124,999 float4 stores

// Block roles in the single fused kernel (1024 threads each):
//   block 0                  : spin on reduction, f_grid slice j + loss
//   blocks 1 .. RED_BLOCKS   : projections + sum|theta| + theta passthrough
//   blocks RED_BLOCKS+1 ..   : 210MB grid copy (skipping slice j)
#define NTHREADS 1024
#define RED_BLOCKS 64                              // 64*1024 = THETA_ELEMS exactly
#define TOTAL_BLOCKS 2369
#define COPY_BLOCKS (TOTAL_BLOCKS - 1 - RED_BLOCKS) // 2304

// Per-block partials [block][0..4]=s[n], [5]=sum|theta| + completion counter.
__device__ float g_part[RED_BLOCKS][6];
__device__ int g_done;                             // zero-initialized; reset each launch

__device__ __forceinline__ void store_group(float4 v, int i, int lo, int hi,
                                            float4* __restrict__ dst4,
                                            float* __restrict__ out) {
    int b = i * 4 + PEEL;                          // absolute float index in grid
    if (b + 4 <= lo || b >= hi) {
        __stcs(dst4 + i, v);                       // common path
    } else if (!(b >= lo && b + 4 <= hi)) {
        // straddles slice boundary: scalar stores of outside floats
        float vals[4] = {v.x, v.y, v.z, v.w};
#pragma unroll
        for (int p = 0; p < 4; p++) {
            int e = b + p;
            if (e < lo || e >= hi) out[OUT_GRID_OFF + e] = vals[p];
        }
    } // fully inside slice j: epilogue block writes it
}

__global__ void __launch_bounds__(NTHREADS) fused_all_kernel(
    const float* __restrict__ x,
    const float* __restrict__ theta,
    const float* __restrict__ grid,
    const int* __restrict__ jp,
    float* __restrict__ out) {

    const int bid = blockIdx.x;
    const int tid = threadIdx.x;
    const int lane = tid & 31;
    const int warp = tid >> 5;
    const int j = __ldg(jp);
    const int lo = j * F_ELEMS;
    const int hi = lo + F_ELEMS;

    if (bid == 0) {
        // ================= epilogue: spin, then fgrid + loss ================
        if (tid == 0) {
            while (atomicAdd(&g_done, 0) < RED_BLOCKS) __nanosleep(64);
            __threadfence();
        }
        __syncthreads();

        // sum the 64 per-block partials: 6 warps, one component each
        __shared__ float s_final[6];
        if (warp < 6) {
            float v = 0.f;
            for (int b = lane; b < RED_BLOCKS; b += 32) v += g_part[b][warp];
#pragma unroll
            for (int o = 16; o; o >>= 1) v += __shfl_down_sync(0xffffffffu, v, o);
            if (lane == 0) s_final[warp] = v;
        }
        __syncthreads();
        if (tid == 0) atomicExch(&g_done, 0);      // reset for next replay

        float s_local[5];
#pragma unroll
        for (int n = 0; n < 5; n++) s_local[n] = s_final[n];
        const float sum_abs = s_final[5];

        const float TWO_PI = 6.2831853071795864769f;
        const float dy = 0.18f / 6.0f;             // 0.03
        const float dz = 0.18f / 5.0f;             // 0.036
        const float dw = 0.2f / 4.0f;              // 0.05
        const float wbase = (TWO_PI / 24.0f) * dy * dz * dw;

        float* gout = out + OUT_GRID_OFF + lo;

        float partial = 0.0f;
        for (int i = tid; i < F_ELEMS; i += NTHREADS) {
            int d = i % NW;
            int c = (i / NW) % NZ;
            int b = (i / (NW * NZ)) % NY;
            int a = (i / (NW * NZ * NY)) % NX;
            int n = i / (NW * NZ * NY * NX);

            float xv = TWO_PI * (float)a / 24.0f;
            float yv = -0.09f + dy * (float)b;
            float zv = -0.09f + dz * (float)c;
            float wv = 0.9f + dw * (float)d;

            float arg = s_local[n] * __cosf(xv) * wv + yv + zv;
            float f = __expf(-arg * arg);
            gout[i] = f;

            float w = wbase;
            if (a == 0 || a == NX - 1) w *= 0.5f;
            if (b == 0 || b == NY - 1) w *= 0.5f;
            if (c == 0 || c == NZ - 1) w *= 0.5f;
            if (d == 0 || d == NW - 1) w *= 0.5f;
            partial += f * w;
        }

        __shared__ float sm[32];
        float v = partial;
#pragma unroll
        for (int o = 16; o; o >>= 1) v += __shfl_down_sync(0xffffffffu, v, o);
        if (lane == 0) sm[warp] = v;
        __syncthreads();
        if (warp == 0) {
            float t = sm[lane];
#pragma unroll
            for (int o = 16; o; o >>= 1) t += __shfl_down_sync(0xffffffffu, t, o);
            if (lane == 0) out[0] = t - 0.5f * sum_abs;
        }
        return;
    }

    if (bid <= RED_BLOCKS) {
        // ============ reduction: 64 blocks * 1024 thr = 65536 elems =========
        const int rb = bid - 1;
        const int k = rb * NTHREADS + tid;         // exactly one element each
        float a = __ldg(theta + k);
        out[1 + k] = a;                            // theta passthrough
        float acc[6];
        acc[5] = fabsf(a);
#pragma unroll
        for (int n = 0; n < 5; n++)
            acc[n] = __ldg(x + n * THETA_ELEMS + k) * a;

        __shared__ float sm[6][32];
#pragma unroll
        for (int i = 0; i < 6; i++) {
            float v = acc[i];
#pragma unroll
            for (int o = 16; o; o >>= 1) v += __shfl_down_sync(0xffffffffu, v, o);
            if (lane == 0) sm[i][warp] = v;
        }
        __syncthreads();
        if (warp == 0) {
#pragma unroll
            for (int i = 0; i < 6; i++) {
                float v = sm[i][lane];
#pragma unroll
                for (int o = 16; o; o >>= 1) v += __shfl_down_sync(0xffffffffu, v, o);
                if (lane == 0) g_part[rb][i] = v;
            }
            if (lane == 0) {
                __threadfence();
                atomicAdd(&g_done, 1);             // release to epilogue block
            }
        }
        return;
    }

    // ================= grid copy (skip slice j), unroll x4 ==================
    const int cb = bid - 1 - RED_BLOCKS;
    const int S = COPY_BLOCKS * NTHREADS;          // 2,359,296
    int i = cb * NTHREADS + tid;

    const float* __restrict__ src = grid + PEEL;
    float4* __restrict__ dst4 = (float4*)(out + OUT_GRID_OFF + PEEL);

    for (; i + 3 * S < NVEC4; i += 4 * S) {
        int i0 = i, i1 = i + S, i2 = i + 2 * S, i3 = i + 3 * S;
        float4 v0, v1, v2, v3;
        // front-batched streaming loads (16 outstanding LDGs)
        v0.x = __ldcs(src + i0 * 4 + 0); v0.y = __ldcs(src + i0 * 4 + 1);
        v0.z = __ldcs(src + i0 * 4 + 2); v0.w = __ldcs(src + i0 * 4 + 3);
        v1.x = __ldcs(src + i1 * 4 + 0); v1.y = __ldcs(src + i1 * 4 + 1);
        v1.z = __ldcs(src + i1 * 4 + 2); v1.w = __ldcs(src + i1 * 4 + 3);
        v2.x = __ldcs(src + i2 * 4 + 0); v2.y = __ldcs(src + i2 * 4 + 1);
        v2.z = __ldcs(src + i2 * 4 + 2); v2.w = __ldcs(src + i2 * 4 + 3);
        v3.x = __ldcs(src + i3 * 4 + 0); v3.y = __ldcs(src + i3 * 4 + 1);
        v3.z = __ldcs(src + i3 * 4 + 2); v3.w = __ldcs(src + i3 * 4 + 3);
        store_group(v0, i0, lo, hi, dst4, out);
        store_group(v1, i1, lo, hi, dst4, out);
        store_group(v2, i2, lo, hi, dst4, out);
        store_group(v3, i3, lo, hi, dst4, out);
    }
    for (; i < NVEC4; i += S) {
        float4 v;
        v.x = __ldcs(src + i * 4 + 0); v.y = __ldcs(src + i * 4 + 1);
        v.z = __ldcs(src + i * 4 + 2); v.w = __ldcs(src + i * 4 + 3);
        store_group(v, i, lo, hi, dst4, out);
    }

    // peel head (3 floats) + tail (1 float): one thread, slice-aware
    if (cb == 0 && tid == 0) {
#pragma unroll
        for (int p = 0; p < PEEL; p++)
            if (p < lo || p >= hi) out[OUT_GRID_OFF + p] = grid[p];
        int tail = PEEL + NVEC4 * 4;               // == GRID_ELEMS - 1
        if (tail < lo || tail >= hi) out[OUT_GRID_OFF + tail] = grid[tail];
    }
}

extern "C" void kernel_launch(void* const* d_in, const int* in_sizes, int n_in,
                              void* d_out, int out_size) {
    const float* x     = (const float*)d_in[0];   // [5,256,256]
    const float* theta = (const float*)d_in[1];   // [1,256,256]
    const float* grid  = (const float*)d_in[2];   // [2000,5,25,7,6,5]
    const int*   jp    = (const int*)d_in[3];     // scalar j

    float* out = (float*)d_out;

    fused_all_kernel<<<TOTAL_BLOCKS, NTHREADS>>>(x, theta, grid, jp, out);
}